// round 2
// baseline (speedup 1.0000x reference)
#include <cuda_runtime.h>

#define BB 16
#define NN 256
#define DM 512
#define HH 8
#define DK 64

// Scratch (allocation-free rule: __device__ globals)
__device__ float g_q[BB*NN*DM];
__device__ float g_k[BB*NN*DM];
__device__ float g_v[BB*NN*DM];
__device__ float g_bias[BB*HH*NN*NN];   // log(max(relu(w_g),1e-6))
__device__ float g_att[BB*NN*DM];       // attention output pre-Wo

__constant__ float c_dim[8] = {
    1.0f, 0.421696503f, 0.177827941f, 0.0749894209f,
    0.0316227766f, 0.0133352143f, 0.00562341325f, 0.00237137371f};

// ---------------------------------------------------------------------------
// GEMM: C[M,Nc] = A[M,K] @ W[K,Nc] + bias[Nc]
// 128x128 block tile, BK=8, 256 threads, 8x8 per thread.
// ---------------------------------------------------------------------------
__global__ __launch_bounds__(256) void gemm_bias_kernel(
    const float* __restrict__ A, const float* __restrict__ W,
    const float* __restrict__ bias, float* __restrict__ C,
    int M, int Nc, int K)
{
    __shared__ float As[8][128];   // [k][m]
    __shared__ float Bs[8][128];   // [k][n]

    const int tid = threadIdx.x;
    const int tx = tid & 15;       // 0..15 -> n
    const int ty = tid >> 4;       // 0..15 -> m
    const int bm = blockIdx.y * 128;
    const int bn = blockIdx.x * 128;

    float acc[8][8];
    #pragma unroll
    for (int i = 0; i < 8; i++)
        #pragma unroll
        for (int j = 0; j < 8; j++) acc[i][j] = 0.f;

    for (int k0 = 0; k0 < K; k0 += 8) {
        // A tile: 128 rows x 8 cols -> 256 float4 loads (transposed store)
        {
            int r = tid >> 1;                 // 0..127
            int cg = (tid & 1) * 4;           // 0 or 4
            const float4 f = *reinterpret_cast<const float4*>(
                &A[(size_t)(bm + r) * K + k0 + cg]);
            As[cg + 0][r] = f.x;
            As[cg + 1][r] = f.y;
            As[cg + 2][r] = f.z;
            As[cg + 3][r] = f.w;
        }
        // B tile: 8 rows x 128 cols -> 256 float4 loads (direct store)
        {
            int r = tid >> 5;                 // 0..7
            int cg = (tid & 31) * 4;          // 0..124
            const float4 f = *reinterpret_cast<const float4*>(
                &W[(size_t)(k0 + r) * Nc + bn + cg]);
            *reinterpret_cast<float4*>(&Bs[r][cg]) = f;
        }
        __syncthreads();

        #pragma unroll
        for (int kk = 0; kk < 8; kk++) {
            float4 a0 = *reinterpret_cast<const float4*>(&As[kk][ty * 8]);
            float4 a1 = *reinterpret_cast<const float4*>(&As[kk][ty * 8 + 4]);
            float4 b0 = *reinterpret_cast<const float4*>(&Bs[kk][tx * 8]);
            float4 b1 = *reinterpret_cast<const float4*>(&Bs[kk][tx * 8 + 4]);
            float a[8] = {a0.x, a0.y, a0.z, a0.w, a1.x, a1.y, a1.z, a1.w};
            float b[8] = {b0.x, b0.y, b0.z, b0.w, b1.x, b1.y, b1.z, b1.w};
            #pragma unroll
            for (int i = 0; i < 8; i++)
                #pragma unroll
                for (int j = 0; j < 8; j++)
                    acc[i][j] += a[i] * b[j];
        }
        __syncthreads();
    }

    #pragma unroll
    for (int i = 0; i < 8; i++) {
        int row = bm + ty * 8 + i;
        #pragma unroll
        for (int j = 0; j < 8; j++) {
            int col = bn + tx * 8 + j;
            C[(size_t)row * Nc + col] = acc[i][j] + bias[col];
        }
    }
}

// ---------------------------------------------------------------------------
// Geometric bias: block per (q, b), 256 threads = keys.
// bias[b,h,q,m] = log(max(relu(geo(b,q,m,:) . WG_w[h,:] + WG_b[h]), 1e-6))
// ---------------------------------------------------------------------------
__global__ __launch_bounds__(256) void geo_bias(
    const float* __restrict__ box, const float* __restrict__ WGw,
    const float* __restrict__ WGb)
{
    __shared__ float sW[HH * 64];
    __shared__ float sB[HH];
    const int b = blockIdx.y;
    const int q = blockIdx.x;
    const int m = threadIdx.x;    // key index 0..255

    sW[m] = WGw[m];
    sW[m + 256] = WGw[m + 256];
    if (m < HH) sB[m] = WGb[m];
    __syncthreads();

    const float* bq = box + ((size_t)b * NN + q) * 4;
    const float x0q = bq[0], y0q = bq[1], x1q = bq[2], y1q = bq[3];
    const float cxq = (x0q + x1q) * 0.5f, cyq = (y0q + y1q) * 0.5f;
    const float wq = x1q - x0q + 1.0f,   hq = y1q - y0q + 1.0f;

    const float* bmp = box + ((size_t)b * NN + m) * 4;
    const float x0m = bmp[0], y0m = bmp[1], x1m = bmp[2], y1m = bmp[3];
    const float cxm = (x0m + x1m) * 0.5f, cym = (y0m + y1m) * 0.5f;
    const float wm = x1m - x0m + 1.0f,    hm = y1m - y0m + 1.0f;

    float delta[4];
    delta[0] = logf(fmaxf(fabsf((cxq - cxm) / wq), 0.001f));
    delta[1] = logf(fmaxf(fabsf((cyq - cym) / hq), 0.001f));
    delta[2] = logf(wq / wm);
    delta[3] = logf(hq / hm);

    float acc[HH];
    #pragma unroll
    for (int h = 0; h < HH; h++) acc[h] = sB[h];

    #pragma unroll
    for (int p = 0; p < 4; p++) {
        #pragma unroll
        for (int f = 0; f < 8; f++) {
            float ang = 100.0f * delta[p] * c_dim[f];
            // explicit range reduction so fast-math sincos stays accurate
            float r = ang - 6.28318530717958647692f *
                            rintf(ang * 0.15915494309189533577f);
            float s, c;
            sincosf(r, &s, &c);
            const int idx = p * 8 + f;
            #pragma unroll
            for (int h = 0; h < HH; h++)
                acc[h] += s * sW[h * 64 + idx] + c * sW[h * 64 + 32 + idx];
        }
    }

    #pragma unroll
    for (int h = 0; h < HH; h++) {
        g_bias[(((size_t)b * HH + h) * NN + q) * NN + m] =
            logf(fmaxf(acc[h], 1e-6f));
    }
}

// ---------------------------------------------------------------------------
// Attention: block per (q, h, b). 128 threads.
// ---------------------------------------------------------------------------
__global__ __launch_bounds__(128) void attn_kernel(const int* __restrict__ mask)
{
    const int qi = blockIdx.x;
    const int h  = blockIdx.y;
    const int b  = blockIdx.z;
    const int t  = threadIdx.x;
    const int warp = t >> 5, lane = t & 31;

    __shared__ float qv[DK];
    __shared__ float sc[NN];
    __shared__ float red[128];

    const float* qp = g_q + ((size_t)b * NN + qi) * DM + h * DK;
    if (t < DK) qv[t] = qp[t];
    __syncthreads();

    const float* Kb = g_k + (size_t)b * NN * DM + h * DK;
    const float* biasrow = g_bias + (((size_t)b * HH + h) * NN + qi) * NN;
    const int* mk = mask + (size_t)b * NN;

    // warp-per-key: warp w handles keys [w*64, w*64+64)
    for (int i = 0; i < 64; i++) {
        const int key = warp * 64 + i;
        const float* kp = Kb + (size_t)key * DM;
        float pal = qv[lane] * kp[lane] + qv[lane + 32] * kp[lane + 32];
        #pragma unroll
        for (int o = 16; o > 0; o >>= 1)
            pal += __shfl_down_sync(0xffffffffu, pal, o);
        if (lane == 0) {
            float sd = pal * 0.125f;             // 1/sqrt(64)
            if (mk[key] == 0) sd = -1e9f;
            sc[key] = sd + biasrow[key];
        }
    }
    __syncthreads();

    // softmax: max
    red[t] = fmaxf(sc[t], sc[t + 128]);
    __syncthreads();
    #pragma unroll
    for (int s = 64; s > 0; s >>= 1) {
        if (t < s) red[t] = fmaxf(red[t], red[t + s]);
        __syncthreads();
    }
    const float mx = red[0];
    __syncthreads();

    // exp + sum
    float e0 = expf(sc[t] - mx);
    float e1 = expf(sc[t + 128] - mx);
    sc[t] = e0;
    sc[t + 128] = e1;
    red[t] = e0 + e1;
    __syncthreads();
    #pragma unroll
    for (int s = 64; s > 0; s >>= 1) {
        if (t < s) red[t] += red[t + s];
        __syncthreads();
    }
    const float inv = 1.0f / red[0];
    __syncthreads();

    // PV: threads [0,64) handle keys [0,128); threads [64,128) keys [128,256)
    const int d = t & 63, half = t >> 6;
    const float* Vb = g_v + (size_t)b * NN * DM + h * DK + d;
    float acc = 0.f;
    const int kbeg = half * 128;
    for (int k = kbeg; k < kbeg + 128; k++)
        acc += sc[k] * Vb[(size_t)k * DM];
    red[t] = acc;
    __syncthreads();
    if (t < 64)
        g_att[((size_t)b * NN + qi) * DM + h * DK + t] =
            (red[t] + red[t + 64]) * inv;
}

// ---------------------------------------------------------------------------
extern "C" void kernel_launch(void* const* d_in, const int* in_sizes, int n_in,
                              void* d_out, int out_size)
{
    const float* xq  = (const float*)d_in[0];
    const float* xk  = (const float*)d_in[1];
    const float* xv  = (const float*)d_in[2];
    const float* box = (const float*)d_in[3];
    const int*   msk = (const int*)  d_in[4];
    const float* Wq  = (const float*)d_in[5];
    const float* bq  = (const float*)d_in[6];
    const float* Wk  = (const float*)d_in[7];
    const float* bk  = (const float*)d_in[8];
    const float* Wv  = (const float*)d_in[9];
    const float* bv  = (const float*)d_in[10];
    const float* Wo  = (const float*)d_in[11];
    const float* bo  = (const float*)d_in[12];
    const float* WGw = (const float*)d_in[13];
    const float* WGb = (const float*)d_in[14];

    float* out = (float*)d_out;

    void *pq, *pk, *pv, *pa;
    cudaGetSymbolAddress(&pq, g_q);
    cudaGetSymbolAddress(&pk, g_k);
    cudaGetSymbolAddress(&pv, g_v);
    cudaGetSymbolAddress(&pa, g_att);

    const int M = BB * NN;           // 4096
    dim3 ggrid(DM / 128, M / 128);   // (4, 32)

    gemm_bias_kernel<<<ggrid, 256>>>(xq, Wq, bq, (float*)pq, M, DM, DM);
    gemm_bias_kernel<<<ggrid, 256>>>(xk, Wk, bk, (float*)pk, M, DM, DM);
    gemm_bias_kernel<<<ggrid, 256>>>(xv, Wv, bv, (float*)pv, M, DM, DM);

    geo_bias<<<dim3(NN, BB), 256>>>(box, WGw, WGb);

    attn_kernel<<<dim3(NN, HH, BB), 128>>>(msk);

    gemm_bias_kernel<<<ggrid, 256>>>((const float*)pa, Wo, bo, out, M, DM, DM);
}

// round 3
// speedup vs baseline: 1.2615x; 1.2615x over previous
#include <cuda_runtime.h>
#include <mma.h>

using namespace nvcuda;

#define BB 16
#define NN 256
#define DM 512
#define HH 8
#define DK 64

// Scratch (allocation-free rule: __device__ globals)
__device__ float g_q[BB*NN*DM];
__device__ float g_k[BB*NN*DM];
__device__ float g_v[BB*NN*DM];
__device__ float g_bias[BB*HH*NN*NN];   // clamped relu(w_g)  (NO log — folded into softmax)
__device__ float g_att[BB*NN*DM];       // attention output pre-Wo

__constant__ float c_dim[8] = {
    1.0f, 0.421696503f, 0.177827941f, 0.0749894209f,
    0.0316227766f, 0.0133352143f, 0.00562341325f, 0.00237137371f};

// ---------------------------------------------------------------------------
// TF32 tensor-core GEMM with 2-term precision split (Markidis):
//   C = Ahi*Bhi + Ahi*Blo + Alo*Bhi   (error ~2^-21, fp32-class)
// C[M,Nc] = A[M,K] @ W[K,Nc]     (bias added by separate kernel)
// Block tile 128x128, BK=16, 256 threads (8 warps: 2x4), warp tile 64x32.
// ---------------------------------------------------------------------------
__global__ __launch_bounds__(256) void gemm_tf32(
    const float* __restrict__ A, const float* __restrict__ W,
    float* __restrict__ C, int M, int Nc, int K)
{
    __shared__ float Ah[128][24];   // [m][k], stride 24 (mult of 8)
    __shared__ float Al[128][24];
    __shared__ float Bh[16][136];   // [k][n], stride 136 (mult of 8)
    __shared__ float Bl[16][136];

    const int tid  = threadIdx.x;
    const int warp = tid >> 5;
    const int wm   = warp >> 2;     // 0..1
    const int wn   = warp & 3;      // 0..3
    const int bm   = blockIdx.y * 128;
    const int bn   = blockIdx.x * 128;

    wmma::fragment<wmma::accumulator, 16, 16, 8, float> acc[4][2];
    #pragma unroll
    for (int i = 0; i < 4; i++)
        #pragma unroll
        for (int j = 0; j < 2; j++)
            wmma::fill_fragment(acc[i][j], 0.0f);

    for (int k0 = 0; k0 < K; k0 += 16) {
        // A tile: 128 rows x 16 cols. thread -> row=tid/2, 8 cols.
        {
            const int row = tid >> 1;
            const int c0  = (tid & 1) * 8;
            const float* ap = &A[(size_t)(bm + row) * K + k0 + c0];
            float4 f0 = *reinterpret_cast<const float4*>(ap);
            float4 f1 = *reinterpret_cast<const float4*>(ap + 4);
            float v[8] = {f0.x, f0.y, f0.z, f0.w, f1.x, f1.y, f1.z, f1.w};
            #pragma unroll
            for (int i = 0; i < 8; i++) {
                float hi = wmma::__float_to_tf32(v[i]);
                Ah[row][c0 + i] = hi;
                Al[row][c0 + i] = v[i] - hi;
            }
        }
        // B tile: 16 rows x 128 cols. thread -> row=tid/16, 8 cols.
        {
            const int row = tid >> 4;
            const int c0  = (tid & 15) * 8;
            const float* bp = &W[(size_t)(k0 + row) * Nc + bn + c0];
            float4 f0 = *reinterpret_cast<const float4*>(bp);
            float4 f1 = *reinterpret_cast<const float4*>(bp + 4);
            float v[8] = {f0.x, f0.y, f0.z, f0.w, f1.x, f1.y, f1.z, f1.w};
            #pragma unroll
            for (int i = 0; i < 8; i++) {
                float hi = wmma::__float_to_tf32(v[i]);
                Bh[row][c0 + i] = hi;
                Bl[row][c0 + i] = v[i] - hi;
            }
        }
        __syncthreads();

        #pragma unroll
        for (int ks = 0; ks < 16; ks += 8) {
            wmma::fragment<wmma::matrix_a, 16, 16, 8, wmma::precision::tf32,
                           wmma::row_major> ah[4], al[4];
            wmma::fragment<wmma::matrix_b, 16, 16, 8, wmma::precision::tf32,
                           wmma::row_major> bh[2], bl[2];
            #pragma unroll
            for (int i = 0; i < 4; i++) {
                wmma::load_matrix_sync(ah[i], &Ah[wm * 64 + i * 16][ks], 24);
                wmma::load_matrix_sync(al[i], &Al[wm * 64 + i * 16][ks], 24);
                #pragma unroll
                for (int t = 0; t < ah[i].num_elements; t++)
                    al[i].x[t] = wmma::__float_to_tf32(al[i].x[t]);
            }
            #pragma unroll
            for (int j = 0; j < 2; j++) {
                wmma::load_matrix_sync(bh[j], &Bh[ks][wn * 32 + j * 16], 136);
                wmma::load_matrix_sync(bl[j], &Bl[ks][wn * 32 + j * 16], 136);
                #pragma unroll
                for (int t = 0; t < bh[j].num_elements; t++)
                    bl[j].x[t] = wmma::__float_to_tf32(bl[j].x[t]);
            }
            #pragma unroll
            for (int i = 0; i < 4; i++)
                #pragma unroll
                for (int j = 0; j < 2; j++) {
                    wmma::mma_sync(acc[i][j], ah[i], bh[j], acc[i][j]);
                    wmma::mma_sync(acc[i][j], ah[i], bl[j], acc[i][j]);
                    wmma::mma_sync(acc[i][j], al[i], bh[j], acc[i][j]);
                }
        }
        __syncthreads();
    }

    #pragma unroll
    for (int i = 0; i < 4; i++)
        #pragma unroll
        for (int j = 0; j < 2; j++) {
            const int row = bm + wm * 64 + i * 16;
            const int col = bn + wn * 32 + j * 16;
            wmma::store_matrix_sync(&C[(size_t)row * Nc + col], acc[i][j],
                                    Nc, wmma::mem_row_major);
        }
}

// ---------------------------------------------------------------------------
// bias add: C[4096,512] += bias[512] (vectorized float4)
// ---------------------------------------------------------------------------
__global__ __launch_bounds__(256) void bias_add(
    float* __restrict__ C, const float* __restrict__ bias)
{
    const int i = blockIdx.x * 256 + threadIdx.x;   // float4 index
    float4 v = reinterpret_cast<float4*>(C)[i];
    const float4 bv = reinterpret_cast<const float4*>(bias)[i & 127];
    v.x += bv.x; v.y += bv.y; v.z += bv.z; v.w += bv.w;
    reinterpret_cast<float4*>(C)[i] = v;
}

// ---------------------------------------------------------------------------
// Geometric weights: block per (q, b), 256 threads = keys.
// Stores clamped relu weight directly (log folded into softmax algebra).
// ---------------------------------------------------------------------------
__global__ __launch_bounds__(256) void geo_bias(
    const float* __restrict__ box, const float* __restrict__ WGw,
    const float* __restrict__ WGb)
{
    __shared__ float sW[HH * 64];
    __shared__ float sB[HH];
    const int b = blockIdx.y;
    const int q = blockIdx.x;
    const int m = threadIdx.x;

    sW[m] = WGw[m];
    sW[m + 256] = WGw[m + 256];
    if (m < HH) sB[m] = WGb[m];
    __syncthreads();

    const float* bq = box + ((size_t)b * NN + q) * 4;
    const float x0q = bq[0], y0q = bq[1], x1q = bq[2], y1q = bq[3];
    const float cxq = (x0q + x1q) * 0.5f, cyq = (y0q + y1q) * 0.5f;
    const float wq = x1q - x0q + 1.0f,   hq = y1q - y0q + 1.0f;

    const float* bmp = box + ((size_t)b * NN + m) * 4;
    const float x0m = bmp[0], y0m = bmp[1], x1m = bmp[2], y1m = bmp[3];
    const float cxm = (x0m + x1m) * 0.5f, cym = (y0m + y1m) * 0.5f;
    const float wm = x1m - x0m + 1.0f,    hm = y1m - y0m + 1.0f;

    float delta[4];
    delta[0] = logf(fmaxf(fabsf((cxq - cxm) / wq), 0.001f));
    delta[1] = logf(fmaxf(fabsf((cyq - cym) / hq), 0.001f));
    delta[2] = logf(wq / wm);
    delta[3] = logf(hq / hm);

    float acc[HH];
    #pragma unroll
    for (int h = 0; h < HH; h++) acc[h] = sB[h];

    #pragma unroll
    for (int p = 0; p < 4; p++) {
        #pragma unroll
        for (int f = 0; f < 8; f++) {
            float ang = 100.0f * delta[p] * c_dim[f];
            float r = ang - 6.28318530717958647692f *
                            rintf(ang * 0.15915494309189533577f);
            float s, c;
            sincosf(r, &s, &c);
            const int idx = p * 8 + f;
            #pragma unroll
            for (int h = 0; h < HH; h++)
                acc[h] += s * sW[h * 64 + idx] + c * sW[h * 64 + 32 + idx];
        }
    }

    #pragma unroll
    for (int h = 0; h < HH; h++) {
        g_bias[(((size_t)b * HH + h) * NN + q) * NN + m] =
            fmaxf(acc[h], 1e-6f);          // = max(relu(wg), 1e-6)
    }
}

// ---------------------------------------------------------------------------
// Flash-style attention: block per (qtile=64, h, b), 256 threads.
// K/V tiles of 32 keys; online softmax with weights = wg * exp(sd - m).
// ---------------------------------------------------------------------------
__global__ __launch_bounds__(256) void attn2(const int* __restrict__ mask)
{
    const int qt = blockIdx.x, h = blockIdx.y, b = blockIdx.z;
    const int qb = qt * 64;
    const int tid = threadIdx.x;

    __shared__ float sQT[64][64];   // [d][q], pre-scaled by 1/sqrt(dk)
    __shared__ float sKT[64][32];   // [d][k]
    __shared__ float sV [32][64];   // [k][d]
    __shared__ float sP [64][32];   // weight tile
    __shared__ float sM[64], sL[64], sScale[64];

    // load Q tile (transposed, pre-scaled)
    {
        const int q  = tid >> 2;
        const int d0 = (tid & 3) * 16;
        const float* qp = g_q + ((size_t)(b * NN + qb + q)) * DM + h * DK + d0;
        #pragma unroll
        for (int g = 0; g < 4; g++) {
            float4 f = *reinterpret_cast<const float4*>(qp + g * 4);
            sQT[d0 + g*4 + 0][q] = f.x * 0.125f;
            sQT[d0 + g*4 + 1][q] = f.y * 0.125f;
            sQT[d0 + g*4 + 2][q] = f.z * 0.125f;
            sQT[d0 + g*4 + 3][q] = f.w * 0.125f;
        }
    }
    if (tid < 64) { sM[tid] = -3.0e38f; sL[tid] = 0.0f; }

    const int tq = tid >> 4;          // 0..15
    const int tk = tid & 15;          // 0..15
    const int q0 = tq * 4;
    const int k0 = tk * 2;
    const int d0 = tk * 4;            // PV phase reuses (tq, tk) as (tq, td)
    const int* mk = mask + b * NN;
    const float* wgb = g_bias + ((size_t)(b * HH + h) * NN) * NN;

    float acc[4][4];
    #pragma unroll
    for (int i = 0; i < 4; i++)
        #pragma unroll
        for (int j = 0; j < 4; j++) acc[i][j] = 0.f;

    for (int kt = 0; kt < 8; kt++) {
        const int kg0 = kt * 32;
        __syncthreads();
        // load K (transposed) + V (natural): 8 floats each per thread
        {
            const int k  = tid >> 3;
            const int dd = (tid & 7) * 8;
            const float* kp = g_k + ((size_t)(b * NN + kg0 + k)) * DM + h * DK + dd;
            float4 f0 = *reinterpret_cast<const float4*>(kp);
            float4 f1 = *reinterpret_cast<const float4*>(kp + 4);
            sKT[dd + 0][k] = f0.x; sKT[dd + 1][k] = f0.y;
            sKT[dd + 2][k] = f0.z; sKT[dd + 3][k] = f0.w;
            sKT[dd + 4][k] = f1.x; sKT[dd + 5][k] = f1.y;
            sKT[dd + 6][k] = f1.z; sKT[dd + 7][k] = f1.w;
            const float* vp = g_v + ((size_t)(b * NN + kg0 + k)) * DM + h * DK + dd;
            *reinterpret_cast<float4*>(&sV[k][dd])     =
                *reinterpret_cast<const float4*>(vp);
            *reinterpret_cast<float4*>(&sV[k][dd + 4]) =
                *reinterpret_cast<const float4*>(vp + 4);
        }
        __syncthreads();

        // scores: 4q x 2k per thread over d=64
        float s00=0,s01=0,s10=0,s11=0,s20=0,s21=0,s30=0,s31=0;
        #pragma unroll 8
        for (int d = 0; d < 64; d++) {
            float4 qa = *reinterpret_cast<const float4*>(&sQT[d][q0]);
            float2 kb = *reinterpret_cast<const float2*>(&sKT[d][k0]);
            s00 += qa.x * kb.x; s01 += qa.x * kb.y;
            s10 += qa.y * kb.x; s11 += qa.y * kb.y;
            s20 += qa.z * kb.x; s21 += qa.z * kb.y;
            s30 += qa.w * kb.x; s31 += qa.w * kb.y;
        }
        float s[4][2] = {{s00,s01},{s10,s11},{s20,s21},{s30,s31}};

        // mask + per-row tile max (reduce over the 16 tk lanes)
        const int km0 = kg0 + k0, km1 = km0 + 1;
        const bool m0 = (mk[km0] == 0), m1 = (mk[km1] == 0);
        float mt[4];
        #pragma unroll
        for (int qi = 0; qi < 4; qi++) {
            if (m0) s[qi][0] = -1e9f;
            if (m1) s[qi][1] = -1e9f;
            mt[qi] = fmaxf(s[qi][0], s[qi][1]);
            #pragma unroll
            for (int o = 1; o < 16; o <<= 1)
                mt[qi] = fmaxf(mt[qi], __shfl_xor_sync(0xffffffffu, mt[qi], o));
        }
        if (tk == 0) {
            #pragma unroll
            for (int qi = 0; qi < 4; qi++) {
                const int q = q0 + qi;
                float m_old = sM[q];
                float m_new = fmaxf(m_old, mt[qi]);
                sM[q] = m_new;
                float scv = __expf(m_old - m_new);
                sScale[q] = scv;
                sL[q] *= scv;
            }
        }
        __syncthreads();

        // weights p = wg * exp(sd - m); row sums
        float sums[4];
        #pragma unroll
        for (int qi = 0; qi < 4; qi++) {
            const int q = q0 + qi;
            const float mq = sM[q];
            float2 wg = *reinterpret_cast<const float2*>(
                &wgb[(size_t)(qb + q) * NN + km0]);
            float p0 = wg.x * __expf(s[qi][0] - mq);
            float p1 = wg.y * __expf(s[qi][1] - mq);
            sP[q][k0]     = p0;
            sP[q][k0 + 1] = p1;
            float su = p0 + p1;
            #pragma unroll
            for (int o = 1; o < 16; o <<= 1)
                su += __shfl_xor_sync(0xffffffffu, su, o);
            sums[qi] = su;
        }
        if (tk == 0) {
            #pragma unroll
            for (int qi = 0; qi < 4; qi++) sL[q0 + qi] += sums[qi];
        }
        __syncthreads();

        // PV: rescale + accumulate (thread = 4q x 4d)
        float sc4[4];
        #pragma unroll
        for (int qi = 0; qi < 4; qi++) sc4[qi] = sScale[q0 + qi];
        #pragma unroll
        for (int qi = 0; qi < 4; qi++)
            #pragma unroll
            for (int dj = 0; dj < 4; dj++) acc[qi][dj] *= sc4[qi];
        #pragma unroll 4
        for (int k = 0; k < 32; k++) {
            float4 v4 = *reinterpret_cast<const float4*>(&sV[k][d0]);
            float p0 = sP[q0 + 0][k];
            float p1 = sP[q0 + 1][k];
            float p2 = sP[q0 + 2][k];
            float p3 = sP[q0 + 3][k];
            acc[0][0] += p0 * v4.x; acc[0][1] += p0 * v4.y;
            acc[0][2] += p0 * v4.z; acc[0][3] += p0 * v4.w;
            acc[1][0] += p1 * v4.x; acc[1][1] += p1 * v4.y;
            acc[1][2] += p1 * v4.z; acc[1][3] += p1 * v4.w;
            acc[2][0] += p2 * v4.x; acc[2][1] += p2 * v4.y;
            acc[2][2] += p2 * v4.z; acc[2][3] += p2 * v4.w;
            acc[3][0] += p3 * v4.x; acc[3][1] += p3 * v4.y;
            acc[3][2] += p3 * v4.z; acc[3][3] += p3 * v4.w;
        }
    }

    // epilogue: normalize and store
    #pragma unroll
    for (int qi = 0; qi < 4; qi++) {
        const int q = q0 + qi;
        const float inv = 1.0f / sL[q];
        float4 o;
        o.x = acc[qi][0] * inv; o.y = acc[qi][1] * inv;
        o.z = acc[qi][2] * inv; o.w = acc[qi][3] * inv;
        *reinterpret_cast<float4*>(
            &g_att[((size_t)(b * NN + qb + q)) * DM + h * DK + d0]) = o;
    }
}

// ---------------------------------------------------------------------------
extern "C" void kernel_launch(void* const* d_in, const int* in_sizes, int n_in,
                              void* d_out, int out_size)
{
    const float* xq  = (const float*)d_in[0];
    const float* xk  = (const float*)d_in[1];
    const float* xv  = (const float*)d_in[2];
    const float* box = (const float*)d_in[3];
    const int*   msk = (const int*)  d_in[4];
    const float* Wq  = (const float*)d_in[5];
    const float* bq  = (const float*)d_in[6];
    const float* Wk  = (const float*)d_in[7];
    const float* bk  = (const float*)d_in[8];
    const float* Wv  = (const float*)d_in[9];
    const float* bv  = (const float*)d_in[10];
    const float* Wo  = (const float*)d_in[11];
    const float* bo  = (const float*)d_in[12];
    const float* WGw = (const float*)d_in[13];
    const float* WGb = (const float*)d_in[14];

    float* out = (float*)d_out;

    void *pq, *pk, *pv, *pa;
    cudaGetSymbolAddress(&pq, g_q);
    cudaGetSymbolAddress(&pk, g_k);
    cudaGetSymbolAddress(&pv, g_v);
    cudaGetSymbolAddress(&pa, g_att);

    const int M = BB * NN;           // 4096
    dim3 ggrid(DM / 128, M / 128);   // (4, 32)
    const int bgrid = (M * DM / 4) / 256;  // float4 grid for bias_add

    gemm_tf32<<<ggrid, 256>>>(xq, Wq, (float*)pq, M, DM, DM);
    bias_add<<<bgrid, 256>>>((float*)pq, bq);
    gemm_tf32<<<ggrid, 256>>>(xk, Wk, (float*)pk, M, DM, DM);
    bias_add<<<bgrid, 256>>>((float*)pk, bk);
    gemm_tf32<<<ggrid, 256>>>(xv, Wv, (float*)pv, M, DM, DM);
    bias_add<<<bgrid, 256>>>((float*)pv, bv);

    geo_bias<<<dim3(NN, BB), 256>>>(box, WGw, WGb);

    attn2<<<dim3(NN / 64, HH, BB), 256>>>(msk);

    gemm_tf32<<<ggrid, 256>>>((const float*)pa, Wo, out, M, DM, DM);
    bias_add<<<bgrid, 256>>>(out, bo);
}

// round 4
// speedup vs baseline: 1.3598x; 1.0779x over previous
#include <cuda_runtime.h>
#include <mma.h>

using namespace nvcuda;

#define BB 16
#define NN 256
#define DM 512
#define HH 8
#define DK 64

// Scratch (allocation-free rule: __device__ globals)
__device__ float g_q[BB*NN*DM];
__device__ float g_k[BB*NN*DM];
__device__ float g_v[BB*NN*DM];
__device__ float g_bias[BB*HH*NN*NN];   // clamped relu(w_g)
__device__ float g_att[BB*NN*DM];       // attention output pre-Wo

__constant__ float c_dim[8] = {
    1.0f, 0.421696503f, 0.177827941f, 0.0749894209f,
    0.0316227766f, 0.0133352143f, 0.00562341325f, 0.00237137371f};

// ---------------------------------------------------------------------------
// Shared TF32 GEMM tile body.
// C[4096,512] = A[4096,512] @ W[512,512] + bias, 2-term Markidis split.
// Block tile 128x128, BK=16, 256 threads (8 warps 2x4), warp tile 64x32.
// lo-residuals pre-rounded to tf32 at staging; ldg pipelined across K-slabs.
// ---------------------------------------------------------------------------
struct GemmSmem {
    float Ah[128][24];
    float Al[128][24];
    float Bh[16][136];
    float Bl[16][136];
};

#define GM 4096
#define GN 512
#define GK 512

__device__ __forceinline__ void gemm_tile(
    GemmSmem& sm,
    const float* __restrict__ A, const float* __restrict__ W,
    const float* __restrict__ bias, float* __restrict__ C)
{
    const int tid  = threadIdx.x;
    const int warp = tid >> 5;
    const int lane = tid & 31;
    const int wm   = warp >> 2;     // 0..1
    const int wn   = warp & 3;      // 0..3
    const int bm   = blockIdx.y * 128;
    const int bn   = blockIdx.x * 128;

    // staging mappings
    const int ar = tid >> 1;              // A row 0..127
    const int ac = (tid & 1) * 8;         // A col group
    const int br = tid >> 4;              // B row 0..15
    const int bc = (tid & 15) * 8;        // B col group

    wmma::fragment<wmma::accumulator, 16, 16, 8, float> acc[4][2];
    #pragma unroll
    for (int i = 0; i < 4; i++)
        #pragma unroll
        for (int j = 0; j < 2; j++)
            wmma::fill_fragment(acc[i][j], 0.0f);

    float va[8], vb[8];
    // prologue ldg (k0 = 0)
    {
        const float* ap = &A[(size_t)(bm + ar) * GK + ac];
        float4 f0 = *reinterpret_cast<const float4*>(ap);
        float4 f1 = *reinterpret_cast<const float4*>(ap + 4);
        va[0]=f0.x; va[1]=f0.y; va[2]=f0.z; va[3]=f0.w;
        va[4]=f1.x; va[5]=f1.y; va[6]=f1.z; va[7]=f1.w;
        const float* bp = &W[(size_t)br * GN + bn + bc];
        float4 g0 = *reinterpret_cast<const float4*>(bp);
        float4 g1 = *reinterpret_cast<const float4*>(bp + 4);
        vb[0]=g0.x; vb[1]=g0.y; vb[2]=g0.z; vb[3]=g0.w;
        vb[4]=g1.x; vb[5]=g1.y; vb[6]=g1.z; vb[7]=g1.w;
    }

    for (int kt = 0; kt < GK / 16; kt++) {
        // stage registers -> smem (hi + tf32-rounded lo)
        #pragma unroll
        for (int i = 0; i < 8; i++) {
            float hi = wmma::__float_to_tf32(va[i]);
            sm.Ah[ar][ac + i] = hi;
            sm.Al[ar][ac + i] = wmma::__float_to_tf32(va[i] - hi);
        }
        #pragma unroll
        for (int i = 0; i < 8; i++) {
            float hi = wmma::__float_to_tf32(vb[i]);
            sm.Bh[br][bc + i] = hi;
            sm.Bl[br][bc + i] = wmma::__float_to_tf32(vb[i] - hi);
        }
        __syncthreads();

        // prefetch next K-slab while mma runs
        if (kt + 1 < GK / 16) {
            const int k0 = (kt + 1) * 16;
            const float* ap = &A[(size_t)(bm + ar) * GK + k0 + ac];
            float4 f0 = *reinterpret_cast<const float4*>(ap);
            float4 f1 = *reinterpret_cast<const float4*>(ap + 4);
            va[0]=f0.x; va[1]=f0.y; va[2]=f0.z; va[3]=f0.w;
            va[4]=f1.x; va[5]=f1.y; va[6]=f1.z; va[7]=f1.w;
            const float* bp = &W[(size_t)(k0 + br) * GN + bn + bc];
            float4 g0 = *reinterpret_cast<const float4*>(bp);
            float4 g1 = *reinterpret_cast<const float4*>(bp + 4);
            vb[0]=g0.x; vb[1]=g0.y; vb[2]=g0.z; vb[3]=g0.w;
            vb[4]=g1.x; vb[5]=g1.y; vb[6]=g1.z; vb[7]=g1.w;
        }

        #pragma unroll
        for (int ks = 0; ks < 16; ks += 8) {
            wmma::fragment<wmma::matrix_a, 16, 16, 8, wmma::precision::tf32,
                           wmma::row_major> ah[4], al[4];
            wmma::fragment<wmma::matrix_b, 16, 16, 8, wmma::precision::tf32,
                           wmma::row_major> bh[2], bl[2];
            #pragma unroll
            for (int i = 0; i < 4; i++) {
                wmma::load_matrix_sync(ah[i], &sm.Ah[wm * 64 + i * 16][ks], 24);
                wmma::load_matrix_sync(al[i], &sm.Al[wm * 64 + i * 16][ks], 24);
            }
            #pragma unroll
            for (int j = 0; j < 2; j++) {
                wmma::load_matrix_sync(bh[j], &sm.Bh[ks][wn * 32 + j * 16], 136);
                wmma::load_matrix_sync(bl[j], &sm.Bl[ks][wn * 32 + j * 16], 136);
            }
            #pragma unroll
            for (int i = 0; i < 4; i++)
                #pragma unroll
                for (int j = 0; j < 2; j++) {
                    wmma::mma_sync(acc[i][j], ah[i], bh[j], acc[i][j]);
                    wmma::mma_sync(acc[i][j], ah[i], bl[j], acc[i][j]);
                    wmma::mma_sync(acc[i][j], al[i], bh[j], acc[i][j]);
                }
        }
        __syncthreads();
    }

    // epilogue: per-warp smem round-trip (reuse Bh/Bl region), fused bias
    float* epib = reinterpret_cast<float*>(sm.Bh) + warp * 288;  // 16x18
    const int er = lane >> 1;           // row 0..15
    const int ec = (lane & 1) * 8;      // col half
    #pragma unroll
    for (int i = 0; i < 4; i++)
        #pragma unroll
        for (int j = 0; j < 2; j++) {
            wmma::store_matrix_sync(epib, acc[i][j], 18, wmma::mem_row_major);
            __syncwarp();
            const int row = bm + wm * 64 + i * 16 + er;
            const int col = bn + wn * 32 + j * 16 + ec;
            float4 b0 = *reinterpret_cast<const float4*>(&bias[col]);
            float4 b1 = *reinterpret_cast<const float4*>(&bias[col + 4]);
            const float* ep = &epib[er * 18 + ec];
            float4 o0 = {ep[0] + b0.x, ep[1] + b0.y, ep[2] + b0.z, ep[3] + b0.w};
            float4 o1 = {ep[4] + b1.x, ep[5] + b1.y, ep[6] + b1.z, ep[7] + b1.w};
            *reinterpret_cast<float4*>(&C[(size_t)row * GN + col])     = o0;
            *reinterpret_cast<float4*>(&C[(size_t)row * GN + col + 4]) = o1;
            __syncwarp();
        }
}

// Fused Q/K/V projections: blockIdx.z selects the triple. 384 blocks.
__global__ __launch_bounds__(256) void gemm_qkv(
    const float* __restrict__ xq, const float* __restrict__ xk,
    const float* __restrict__ xv,
    const float* __restrict__ Wq, const float* __restrict__ Wk,
    const float* __restrict__ Wv,
    const float* __restrict__ bq, const float* __restrict__ bk,
    const float* __restrict__ bv,
    float* __restrict__ oq, float* __restrict__ ok, float* __restrict__ ov)
{
    __shared__ GemmSmem sm;
    const float *A, *W, *bias;
    float* C;
    if (blockIdx.z == 0)      { A = xq; W = Wq; bias = bq; C = oq; }
    else if (blockIdx.z == 1) { A = xk; W = Wk; bias = bk; C = ok; }
    else                      { A = xv; W = Wv; bias = bv; C = ov; }
    gemm_tile(sm, A, W, bias, C);
}

__global__ __launch_bounds__(256) void gemm_one(
    const float* __restrict__ A, const float* __restrict__ W,
    const float* __restrict__ bias, float* __restrict__ C)
{
    __shared__ GemmSmem sm;
    gemm_tile(sm, A, W, bias, C);
}

// ---------------------------------------------------------------------------
// Geometric weights: block per (q, b), 256 threads = keys.
// Stores clamped relu weight directly (log folded into softmax algebra).
// ---------------------------------------------------------------------------
__global__ __launch_bounds__(256) void geo_bias(
    const float* __restrict__ box, const float* __restrict__ WGw,
    const float* __restrict__ WGb)
{
    __shared__ float sW[HH * 64];
    __shared__ float sB[HH];
    const int b = blockIdx.y;
    const int q = blockIdx.x;
    const int m = threadIdx.x;

    sW[m] = WGw[m];
    sW[m + 256] = WGw[m + 256];
    if (m < HH) sB[m] = WGb[m];
    __syncthreads();

    const float* bq = box + ((size_t)b * NN + q) * 4;
    const float x0q = bq[0], y0q = bq[1], x1q = bq[2], y1q = bq[3];
    const float cxq = (x0q + x1q) * 0.5f, cyq = (y0q + y1q) * 0.5f;
    const float wq = x1q - x0q + 1.0f,   hq = y1q - y0q + 1.0f;

    const float* bmp = box + ((size_t)b * NN + m) * 4;
    const float x0m = bmp[0], y0m = bmp[1], x1m = bmp[2], y1m = bmp[3];
    const float cxm = (x0m + x1m) * 0.5f, cym = (y0m + y1m) * 0.5f;
    const float wm = x1m - x0m + 1.0f,    hm = y1m - y0m + 1.0f;

    float delta[4];
    delta[0] = logf(fmaxf(fabsf((cxq - cxm) / wq), 0.001f));
    delta[1] = logf(fmaxf(fabsf((cyq - cym) / hq), 0.001f));
    delta[2] = logf(wq / wm);
    delta[3] = logf(hq / hm);

    float acc[HH];
    #pragma unroll
    for (int h = 0; h < HH; h++) acc[h] = sB[h];

    #pragma unroll
    for (int p = 0; p < 4; p++) {
        #pragma unroll
        for (int f = 0; f < 8; f++) {
            float ang = 100.0f * delta[p] * c_dim[f];
            float r = ang - 6.28318530717958647692f *
                            rintf(ang * 0.15915494309189533577f);
            float s, c;
            sincosf(r, &s, &c);
            const int idx = p * 8 + f;
            #pragma unroll
            for (int h = 0; h < HH; h++)
                acc[h] += s * sW[h * 64 + idx] + c * sW[h * 64 + 32 + idx];
        }
    }

    #pragma unroll
    for (int h = 0; h < HH; h++) {
        g_bias[(((size_t)b * HH + h) * NN + q) * NN + m] =
            fmaxf(acc[h], 1e-6f);
    }
}

// ---------------------------------------------------------------------------
// Flash-style attention: block per (qtile=64, h, b), 256 threads.
// ---------------------------------------------------------------------------
__global__ __launch_bounds__(256) void attn2(const int* __restrict__ mask)
{
    const int qt = blockIdx.x, h = blockIdx.y, b = blockIdx.z;
    const int qb = qt * 64;
    const int tid = threadIdx.x;

    __shared__ float sQT[64][64];
    __shared__ float sKT[64][32];
    __shared__ float sV [32][64];
    __shared__ float sP [64][32];
    __shared__ float sM[64], sL[64], sScale[64];

    {
        const int q  = tid >> 2;
        const int d0 = (tid & 3) * 16;
        const float* qp = g_q + ((size_t)(b * NN + qb + q)) * DM + h * DK + d0;
        #pragma unroll
        for (int g = 0; g < 4; g++) {
            float4 f = *reinterpret_cast<const float4*>(qp + g * 4);
            sQT[d0 + g*4 + 0][q] = f.x * 0.125f;
            sQT[d0 + g*4 + 1][q] = f.y * 0.125f;
            sQT[d0 + g*4 + 2][q] = f.z * 0.125f;
            sQT[d0 + g*4 + 3][q] = f.w * 0.125f;
        }
    }
    if (tid < 64) { sM[tid] = -3.0e38f; sL[tid] = 0.0f; }

    const int tq = tid >> 4;
    const int tk = tid & 15;
    const int q0 = tq * 4;
    const int k0 = tk * 2;
    const int d0 = tk * 4;
    const int* mk = mask + b * NN;
    const float* wgb = g_bias + ((size_t)(b * HH + h) * NN) * NN;

    float acc[4][4];
    #pragma unroll
    for (int i = 0; i < 4; i++)
        #pragma unroll
        for (int j = 0; j < 4; j++) acc[i][j] = 0.f;

    for (int kt = 0; kt < 8; kt++) {
        const int kg0 = kt * 32;
        __syncthreads();
        {
            const int k  = tid >> 3;
            const int dd = (tid & 7) * 8;
            const float* kp = g_k + ((size_t)(b * NN + kg0 + k)) * DM + h * DK + dd;
            float4 f0 = *reinterpret_cast<const float4*>(kp);
            float4 f1 = *reinterpret_cast<const float4*>(kp + 4);
            sKT[dd + 0][k] = f0.x; sKT[dd + 1][k] = f0.y;
            sKT[dd + 2][k] = f0.z; sKT[dd + 3][k] = f0.w;
            sKT[dd + 4][k] = f1.x; sKT[dd + 5][k] = f1.y;
            sKT[dd + 6][k] = f1.z; sKT[dd + 7][k] = f1.w;
            const float* vp = g_v + ((size_t)(b * NN + kg0 + k)) * DM + h * DK + dd;
            *reinterpret_cast<float4*>(&sV[k][dd])     =
                *reinterpret_cast<const float4*>(vp);
            *reinterpret_cast<float4*>(&sV[k][dd + 4]) =
                *reinterpret_cast<const float4*>(vp + 4);
        }
        __syncthreads();

        float s00=0,s01=0,s10=0,s11=0,s20=0,s21=0,s30=0,s31=0;
        #pragma unroll 8
        for (int d = 0; d < 64; d++) {
            float4 qa = *reinterpret_cast<const float4*>(&sQT[d][q0]);
            float2 kb = *reinterpret_cast<const float2*>(&sKT[d][k0]);
            s00 += qa.x * kb.x; s01 += qa.x * kb.y;
            s10 += qa.y * kb.x; s11 += qa.y * kb.y;
            s20 += qa.z * kb.x; s21 += qa.z * kb.y;
            s30 += qa.w * kb.x; s31 += qa.w * kb.y;
        }
        float s[4][2] = {{s00,s01},{s10,s11},{s20,s21},{s30,s31}};

        const int km0 = kg0 + k0, km1 = km0 + 1;
        const bool m0 = (mk[km0] == 0), m1 = (mk[km1] == 0);
        float mt[4];
        #pragma unroll
        for (int qi = 0; qi < 4; qi++) {
            if (m0) s[qi][0] = -1e9f;
            if (m1) s[qi][1] = -1e9f;
            mt[qi] = fmaxf(s[qi][0], s[qi][1]);
            #pragma unroll
            for (int o = 1; o < 16; o <<= 1)
                mt[qi] = fmaxf(mt[qi], __shfl_xor_sync(0xffffffffu, mt[qi], o));
        }
        if (tk == 0) {
            #pragma unroll
            for (int qi = 0; qi < 4; qi++) {
                const int q = q0 + qi;
                float m_old = sM[q];
                float m_new = fmaxf(m_old, mt[qi]);
                sM[q] = m_new;
                float scv = __expf(m_old - m_new);
                sScale[q] = scv;
                sL[q] *= scv;
            }
        }
        __syncthreads();

        float sums[4];
        #pragma unroll
        for (int qi = 0; qi < 4; qi++) {
            const int q = q0 + qi;
            const float mq = sM[q];
            float2 wg = *reinterpret_cast<const float2*>(
                &wgb[(size_t)(qb + q) * NN + km0]);
            float p0 = wg.x * __expf(s[qi][0] - mq);
            float p1 = wg.y * __expf(s[qi][1] - mq);
            sP[q][k0]     = p0;
            sP[q][k0 + 1] = p1;
            float su = p0 + p1;
            #pragma unroll
            for (int o = 1; o < 16; o <<= 1)
                su += __shfl_xor_sync(0xffffffffu, su, o);
            sums[qi] = su;
        }
        if (tk == 0) {
            #pragma unroll
            for (int qi = 0; qi < 4; qi++) sL[q0 + qi] += sums[qi];
        }
        __syncthreads();

        float sc4[4];
        #pragma unroll
        for (int qi = 0; qi < 4; qi++) sc4[qi] = sScale[q0 + qi];
        #pragma unroll
        for (int qi = 0; qi < 4; qi++)
            #pragma unroll
            for (int dj = 0; dj < 4; dj++) acc[qi][dj] *= sc4[qi];
        #pragma unroll 4
        for (int k = 0; k < 32; k++) {
            float4 v4 = *reinterpret_cast<const float4*>(&sV[k][d0]);
            float p0 = sP[q0 + 0][k];
            float p1 = sP[q0 + 1][k];
            float p2 = sP[q0 + 2][k];
            float p3 = sP[q0 + 3][k];
            acc[0][0] += p0 * v4.x; acc[0][1] += p0 * v4.y;
            acc[0][2] += p0 * v4.z; acc[0][3] += p0 * v4.w;
            acc[1][0] += p1 * v4.x; acc[1][1] += p1 * v4.y;
            acc[1][2] += p1 * v4.z; acc[1][3] += p1 * v4.w;
            acc[2][0] += p2 * v4.x; acc[2][1] += p2 * v4.y;
            acc[2][2] += p2 * v4.z; acc[2][3] += p2 * v4.w;
            acc[3][0] += p3 * v4.x; acc[3][1] += p3 * v4.y;
            acc[3][2] += p3 * v4.z; acc[3][3] += p3 * v4.w;
        }
    }

    #pragma unroll
    for (int qi = 0; qi < 4; qi++) {
        const int q = q0 + qi;
        const float inv = 1.0f / sL[q];
        float4 o;
        o.x = acc[qi][0] * inv; o.y = acc[qi][1] * inv;
        o.z = acc[qi][2] * inv; o.w = acc[qi][3] * inv;
        *reinterpret_cast<float4*>(
            &g_att[((size_t)(b * NN + qb + q)) * DM + h * DK + d0]) = o;
    }
}

// ---------------------------------------------------------------------------
extern "C" void kernel_launch(void* const* d_in, const int* in_sizes, int n_in,
                              void* d_out, int out_size)
{
    const float* xq  = (const float*)d_in[0];
    const float* xk  = (const float*)d_in[1];
    const float* xv  = (const float*)d_in[2];
    const float* box = (const float*)d_in[3];
    const int*   msk = (const int*)  d_in[4];
    const float* Wq  = (const float*)d_in[5];
    const float* bq  = (const float*)d_in[6];
    const float* Wk  = (const float*)d_in[7];
    const float* bk  = (const float*)d_in[8];
    const float* Wv  = (const float*)d_in[9];
    const float* bv  = (const float*)d_in[10];
    const float* Wo  = (const float*)d_in[11];
    const float* bo  = (const float*)d_in[12];
    const float* WGw = (const float*)d_in[13];
    const float* WGb = (const float*)d_in[14];

    float* out = (float*)d_out;

    void *pq, *pk, *pv, *pa;
    cudaGetSymbolAddress(&pq, g_q);
    cudaGetSymbolAddress(&pk, g_k);
    cudaGetSymbolAddress(&pv, g_v);
    cudaGetSymbolAddress(&pa, g_att);

    dim3 qkvgrid(GN / 128, GM / 128, 3);    // (4, 32, 3) = 384 blocks

    gemm_qkv<<<qkvgrid, 256>>>(xq, xk, xv, Wq, Wk, Wv, bq, bk, bv,
                               (float*)pq, (float*)pk, (float*)pv);

    geo_bias<<<dim3(NN, BB), 256>>>(box, WGw, WGb);

    attn2<<<dim3(NN / 64, HH, BB), 256>>>(msk);

    gemm_one<<<dim3(GN / 128, GM / 128), 256>>>((const float*)pa, Wo, bo, out);
}

// round 5
// speedup vs baseline: 2.3989x; 1.7642x over previous
#include <cuda_runtime.h>
#include <cuda_bf16.h>
#include <mma.h>

using namespace nvcuda;

#define BB 16
#define NN 256
#define DM 512
#define HH 8
#define DK 64

// Scratch (allocation-free rule: __device__ globals)
__device__ float g_q[BB*NN*DM];
__device__ float g_k[BB*NN*DM];
__device__ float g_v[BB*NN*DM];
__device__ float g_bias[BB*HH*NN*NN];   // clamped relu(w_g)
__device__ float g_att[BB*NN*DM];       // attention output pre-Wo

__constant__ float c_dim[8] = {
    1.0f, 0.421696503f, 0.177827941f, 0.0749894209f,
    0.0316227766f, 0.0133352143f, 0.00562341325f, 0.00237137371f};

// ---------------------------------------------------------------------------
// BF16 tensor-core GEMM, 3-term precision split:
//   C = Ahi*Bhi + Ahi*Blo + Alo*Bhi   (fp16-class accuracy, fp32 accum)
// C[4096,512] = A[4096,512] @ W[512,512] + bias
// Block tile 128x128, BK=16, 256 threads (8 warps 2x4), warp tile 64x32.
// smem ~21KB, __launch_bounds__(256,2) -> 2 CTAs/SM.
// ---------------------------------------------------------------------------
struct GemmSmem {
    __nv_bfloat16 Ah[128][24];   // [m][k], stride 24 (48B rows, 16B aligned)
    __nv_bfloat16 Al[128][24];
    __nv_bfloat16 Bh[16][136];   // [k][n], stride 136 (272B rows)
    __nv_bfloat16 Bl[16][136];
};

#define GM 4096
#define GN 512
#define GK 512

__device__ __forceinline__ void gemm_tile(
    GemmSmem& sm,
    const float* __restrict__ A, const float* __restrict__ W,
    const float* __restrict__ bias, float* __restrict__ C)
{
    const int tid  = threadIdx.x;
    const int warp = tid >> 5;
    const int lane = tid & 31;
    const int wm   = warp >> 2;     // 0..1
    const int wn   = warp & 3;      // 0..3
    const int bm   = blockIdx.y * 128;
    const int bn   = blockIdx.x * 128;

    const int ar = tid >> 1;              // A row 0..127
    const int ac = (tid & 1) * 8;         // A col group
    const int br = tid >> 4;              // B row 0..15
    const int bc = (tid & 15) * 8;        // B col group

    wmma::fragment<wmma::accumulator, 16, 16, 16, float> acc[4][2];
    #pragma unroll
    for (int i = 0; i < 4; i++)
        #pragma unroll
        for (int j = 0; j < 2; j++)
            wmma::fill_fragment(acc[i][j], 0.0f);

    float va[8], vb[8];
    // prologue ldg (k0 = 0)
    {
        const float* ap = &A[(size_t)(bm + ar) * GK + ac];
        float4 f0 = *reinterpret_cast<const float4*>(ap);
        float4 f1 = *reinterpret_cast<const float4*>(ap + 4);
        va[0]=f0.x; va[1]=f0.y; va[2]=f0.z; va[3]=f0.w;
        va[4]=f1.x; va[5]=f1.y; va[6]=f1.z; va[7]=f1.w;
        const float* bp = &W[(size_t)br * GN + bn + bc];
        float4 g0 = *reinterpret_cast<const float4*>(bp);
        float4 g1 = *reinterpret_cast<const float4*>(bp + 4);
        vb[0]=g0.x; vb[1]=g0.y; vb[2]=g0.z; vb[3]=g0.w;
        vb[4]=g1.x; vb[5]=g1.y; vb[6]=g1.z; vb[7]=g1.w;
    }

    for (int kt = 0; kt < GK / 16; kt++) {
        // stage registers -> smem (bf16 hi + bf16 lo residual)
        #pragma unroll
        for (int i = 0; i < 8; i++) {
            __nv_bfloat16 hi = __float2bfloat16(va[i]);
            sm.Ah[ar][ac + i] = hi;
            sm.Al[ar][ac + i] = __float2bfloat16(va[i] - __bfloat162float(hi));
        }
        #pragma unroll
        for (int i = 0; i < 8; i++) {
            __nv_bfloat16 hi = __float2bfloat16(vb[i]);
            sm.Bh[br][bc + i] = hi;
            sm.Bl[br][bc + i] = __float2bfloat16(vb[i] - __bfloat162float(hi));
        }
        __syncthreads();

        // prefetch next K-slab while mma runs
        if (kt + 1 < GK / 16) {
            const int k0 = (kt + 1) * 16;
            const float* ap = &A[(size_t)(bm + ar) * GK + k0 + ac];
            float4 f0 = *reinterpret_cast<const float4*>(ap);
            float4 f1 = *reinterpret_cast<const float4*>(ap + 4);
            va[0]=f0.x; va[1]=f0.y; va[2]=f0.z; va[3]=f0.w;
            va[4]=f1.x; va[5]=f1.y; va[6]=f1.z; va[7]=f1.w;
            const float* bp = &W[(size_t)(k0 + br) * GN + bn + bc];
            float4 g0 = *reinterpret_cast<const float4*>(bp);
            float4 g1 = *reinterpret_cast<const float4*>(bp + 4);
            vb[0]=g0.x; vb[1]=g0.y; vb[2]=g0.z; vb[3]=g0.w;
            vb[4]=g1.x; vb[5]=g1.y; vb[6]=g1.z; vb[7]=g1.w;
        }

        // one k16 pass covers BK=16
        {
            wmma::fragment<wmma::matrix_a, 16, 16, 16, __nv_bfloat16,
                           wmma::row_major> ah[4], al[4];
            wmma::fragment<wmma::matrix_b, 16, 16, 16, __nv_bfloat16,
                           wmma::row_major> bh[2], bl[2];
            #pragma unroll
            for (int i = 0; i < 4; i++) {
                wmma::load_matrix_sync(ah[i], &sm.Ah[wm * 64 + i * 16][0], 24);
                wmma::load_matrix_sync(al[i], &sm.Al[wm * 64 + i * 16][0], 24);
            }
            #pragma unroll
            for (int j = 0; j < 2; j++) {
                wmma::load_matrix_sync(bh[j], &sm.Bh[0][wn * 32 + j * 16], 136);
                wmma::load_matrix_sync(bl[j], &sm.Bl[0][wn * 32 + j * 16], 136);
            }
            #pragma unroll
            for (int i = 0; i < 4; i++)
                #pragma unroll
                for (int j = 0; j < 2; j++) {
                    wmma::mma_sync(acc[i][j], ah[i], bh[j], acc[i][j]);
                    wmma::mma_sync(acc[i][j], ah[i], bl[j], acc[i][j]);
                    wmma::mma_sync(acc[i][j], al[i], bh[j], acc[i][j]);
                }
        }
        __syncthreads();
    }

    // epilogue: per-warp fp32 smem scratch (overlays dead tile data), fused bias
    float* epib = reinterpret_cast<float*>(&sm) + warp * 288;  // 16x18 floats
    const int er = lane >> 1;           // row 0..15
    const int ec = (lane & 1) * 8;      // col half
    #pragma unroll
    for (int i = 0; i < 4; i++)
        #pragma unroll
        for (int j = 0; j < 2; j++) {
            wmma::store_matrix_sync(epib, acc[i][j], 18, wmma::mem_row_major);
            __syncwarp();
            const int row = bm + wm * 64 + i * 16 + er;
            const int col = bn + wn * 32 + j * 16 + ec;
            float4 b0 = *reinterpret_cast<const float4*>(&bias[col]);
            float4 b1 = *reinterpret_cast<const float4*>(&bias[col + 4]);
            const float* ep = &epib[er * 18 + ec];
            float4 o0 = {ep[0] + b0.x, ep[1] + b0.y, ep[2] + b0.z, ep[3] + b0.w};
            float4 o1 = {ep[4] + b1.x, ep[5] + b1.y, ep[6] + b1.z, ep[7] + b1.w};
            *reinterpret_cast<float4*>(&C[(size_t)row * GN + col])     = o0;
            *reinterpret_cast<float4*>(&C[(size_t)row * GN + col + 4]) = o1;
            __syncwarp();
        }
}

// Fused Q/K/V projections: blockIdx.z selects the triple. 384 blocks.
__global__ __launch_bounds__(256, 2) void gemm_qkv(
    const float* __restrict__ xq, const float* __restrict__ xk,
    const float* __restrict__ xv,
    const float* __restrict__ Wq, const float* __restrict__ Wk,
    const float* __restrict__ Wv,
    const float* __restrict__ bq, const float* __restrict__ bk,
    const float* __restrict__ bv,
    float* __restrict__ oq, float* __restrict__ ok, float* __restrict__ ov)
{
    __shared__ GemmSmem sm;
    const float *A, *W, *bias;
    float* C;
    if (blockIdx.z == 0)      { A = xq; W = Wq; bias = bq; C = oq; }
    else if (blockIdx.z == 1) { A = xk; W = Wk; bias = bk; C = ok; }
    else                      { A = xv; W = Wv; bias = bv; C = ov; }
    gemm_tile(sm, A, W, bias, C);
}

__global__ __launch_bounds__(256, 2) void gemm_one(
    const float* __restrict__ A, const float* __restrict__ W,
    const float* __restrict__ bias, float* __restrict__ C)
{
    __shared__ GemmSmem sm;
    gemm_tile(sm, A, W, bias, C);
}

// ---------------------------------------------------------------------------
// Geometric weights: block per (q, b), 256 threads = keys.
// Stores clamped relu weight directly (log folded into softmax algebra).
// ---------------------------------------------------------------------------
__global__ __launch_bounds__(256) void geo_bias(
    const float* __restrict__ box, const float* __restrict__ WGw,
    const float* __restrict__ WGb)
{
    __shared__ float sW[HH * 64];
    __shared__ float sB[HH];
    const int b = blockIdx.y;
    const int q = blockIdx.x;
    const int m = threadIdx.x;

    sW[m] = WGw[m];
    sW[m + 256] = WGw[m + 256];
    if (m < HH) sB[m] = WGb[m];
    __syncthreads();

    const float* bq = box + ((size_t)b * NN + q) * 4;
    const float x0q = bq[0], y0q = bq[1], x1q = bq[2], y1q = bq[3];
    const float cxq = (x0q + x1q) * 0.5f, cyq = (y0q + y1q) * 0.5f;
    const float wq = x1q - x0q + 1.0f,   hq = y1q - y0q + 1.0f;

    const float* bmp = box + ((size_t)b * NN + m) * 4;
    const float x0m = bmp[0], y0m = bmp[1], x1m = bmp[2], y1m = bmp[3];
    const float cxm = (x0m + x1m) * 0.5f, cym = (y0m + y1m) * 0.5f;
    const float wm = x1m - x0m + 1.0f,    hm = y1m - y0m + 1.0f;

    float delta[4];
    delta[0] = logf(fmaxf(fabsf((cxq - cxm) / wq), 0.001f));
    delta[1] = logf(fmaxf(fabsf((cyq - cym) / hq), 0.001f));
    delta[2] = logf(wq / wm);
    delta[3] = logf(hq / hm);

    float acc[HH];
    #pragma unroll
    for (int h = 0; h < HH; h++) acc[h] = sB[h];

    #pragma unroll
    for (int p = 0; p < 4; p++) {
        #pragma unroll
        for (int f = 0; f < 8; f++) {
            float ang = 100.0f * delta[p] * c_dim[f];
            float r = ang - 6.28318530717958647692f *
                            rintf(ang * 0.15915494309189533577f);
            float s, c;
            sincosf(r, &s, &c);
            const int idx = p * 8 + f;
            #pragma unroll
            for (int h = 0; h < HH; h++)
                acc[h] += s * sW[h * 64 + idx] + c * sW[h * 64 + 32 + idx];
        }
    }

    #pragma unroll
    for (int h = 0; h < HH; h++) {
        g_bias[(((size_t)b * HH + h) * NN + q) * NN + m] =
            fmaxf(acc[h], 1e-6f);
    }
}

// ---------------------------------------------------------------------------
// Flash-style attention: block per (qtile=64, h, b), 256 threads.
// ---------------------------------------------------------------------------
__global__ __launch_bounds__(256) void attn2(const int* __restrict__ mask)
{
    const int qt = blockIdx.x, h = blockIdx.y, b = blockIdx.z;
    const int qb = qt * 64;
    const int tid = threadIdx.x;

    __shared__ float sQT[64][64];
    __shared__ float sKT[64][32];
    __shared__ float sV [32][64];
    __shared__ float sP [64][32];
    __shared__ float sM[64], sL[64], sScale[64];

    {
        const int q  = tid >> 2;
        const int d0 = (tid & 3) * 16;
        const float* qp = g_q + ((size_t)(b * NN + qb + q)) * DM + h * DK + d0;
        #pragma unroll
        for (int g = 0; g < 4; g++) {
            float4 f = *reinterpret_cast<const float4*>(qp + g * 4);
            sQT[d0 + g*4 + 0][q] = f.x * 0.125f;
            sQT[d0 + g*4 + 1][q] = f.y * 0.125f;
            sQT[d0 + g*4 + 2][q] = f.z * 0.125f;
            sQT[d0 + g*4 + 3][q] = f.w * 0.125f;
        }
    }
    if (tid < 64) { sM[tid] = -3.0e38f; sL[tid] = 0.0f; }

    const int tq = tid >> 4;
    const int tk = tid & 15;
    const int q0 = tq * 4;
    const int k0 = tk * 2;
    const int d0 = tk * 4;
    const int* mk = mask + b * NN;
    const float* wgb = g_bias + ((size_t)(b * HH + h) * NN) * NN;

    float acc[4][4];
    #pragma unroll
    for (int i = 0; i < 4; i++)
        #pragma unroll
        for (int j = 0; j < 4; j++) acc[i][j] = 0.f;

    for (int kt = 0; kt < 8; kt++) {
        const int kg0 = kt * 32;
        __syncthreads();
        {
            const int k  = tid >> 3;
            const int dd = (tid & 7) * 8;
            const float* kp = g_k + ((size_t)(b * NN + kg0 + k)) * DM + h * DK + dd;
            float4 f0 = *reinterpret_cast<const float4*>(kp);
            float4 f1 = *reinterpret_cast<const float4*>(kp + 4);
            sKT[dd + 0][k] = f0.x; sKT[dd + 1][k] = f0.y;
            sKT[dd + 2][k] = f0.z; sKT[dd + 3][k] = f0.w;
            sKT[dd + 4][k] = f1.x; sKT[dd + 5][k] = f1.y;
            sKT[dd + 6][k] = f1.z; sKT[dd + 7][k] = f1.w;
            const float* vp = g_v + ((size_t)(b * NN + kg0 + k)) * DM + h * DK + dd;
            *reinterpret_cast<float4*>(&sV[k][dd])     =
                *reinterpret_cast<const float4*>(vp);
            *reinterpret_cast<float4*>(&sV[k][dd + 4]) =
                *reinterpret_cast<const float4*>(vp + 4);
        }
        __syncthreads();

        float s00=0,s01=0,s10=0,s11=0,s20=0,s21=0,s30=0,s31=0;
        #pragma unroll 8
        for (int d = 0; d < 64; d++) {
            float4 qa = *reinterpret_cast<const float4*>(&sQT[d][q0]);
            float2 kb = *reinterpret_cast<const float2*>(&sKT[d][k0]);
            s00 += qa.x * kb.x; s01 += qa.x * kb.y;
            s10 += qa.y * kb.x; s11 += qa.y * kb.y;
            s20 += qa.z * kb.x; s21 += qa.z * kb.y;
            s30 += qa.w * kb.x; s31 += qa.w * kb.y;
        }
        float s[4][2] = {{s00,s01},{s10,s11},{s20,s21},{s30,s31}};

        const int km0 = kg0 + k0, km1 = km0 + 1;
        const bool m0 = (mk[km0] == 0), m1 = (mk[km1] == 0);
        float mt[4];
        #pragma unroll
        for (int qi = 0; qi < 4; qi++) {
            if (m0) s[qi][0] = -1e9f;
            if (m1) s[qi][1] = -1e9f;
            mt[qi] = fmaxf(s[qi][0], s[qi][1]);
            #pragma unroll
            for (int o = 1; o < 16; o <<= 1)
                mt[qi] = fmaxf(mt[qi], __shfl_xor_sync(0xffffffffu, mt[qi], o));
        }
        if (tk == 0) {
            #pragma unroll
            for (int qi = 0; qi < 4; qi++) {
                const int q = q0 + qi;
                float m_old = sM[q];
                float m_new = fmaxf(m_old, mt[qi]);
                sM[q] = m_new;
                float scv = __expf(m_old - m_new);
                sScale[q] = scv;
                sL[q] *= scv;
            }
        }
        __syncthreads();

        float sums[4];
        #pragma unroll
        for (int qi = 0; qi < 4; qi++) {
            const int q = q0 + qi;
            const float mq = sM[q];
            float2 wg = *reinterpret_cast<const float2*>(
                &wgb[(size_t)(qb + q) * NN + km0]);
            float p0 = wg.x * __expf(s[qi][0] - mq);
            float p1 = wg.y * __expf(s[qi][1] - mq);
            sP[q][k0]     = p0;
            sP[q][k0 + 1] = p1;
            float su = p0 + p1;
            #pragma unroll
            for (int o = 1; o < 16; o <<= 1)
                su += __shfl_xor_sync(0xffffffffu, su, o);
            sums[qi] = su;
        }
        if (tk == 0) {
            #pragma unroll
            for (int qi = 0; qi < 4; qi++) sL[q0 + qi] += sums[qi];
        }
        __syncthreads();

        float sc4[4];
        #pragma unroll
        for (int qi = 0; qi < 4; qi++) sc4[qi] = sScale[q0 + qi];
        #pragma unroll
        for (int qi = 0; qi < 4; qi++)
            #pragma unroll
            for (int dj = 0; dj < 4; dj++) acc[qi][dj] *= sc4[qi];
        #pragma unroll 4
        for (int k = 0; k < 32; k++) {
            float4 v4 = *reinterpret_cast<const float4*>(&sV[k][d0]);
            float p0 = sP[q0 + 0][k];
            float p1 = sP[q0 + 1][k];
            float p2 = sP[q0 + 2][k];
            float p3 = sP[q0 + 3][k];
            acc[0][0] += p0 * v4.x; acc[0][1] += p0 * v4.y;
            acc[0][2] += p0 * v4.z; acc[0][3] += p0 * v4.w;
            acc[1][0] += p1 * v4.x; acc[1][1] += p1 * v4.y;
            acc[1][2] += p1 * v4.z; acc[1][3] += p1 * v4.w;
            acc[2][0] += p2 * v4.x; acc[2][1] += p2 * v4.y;
            acc[2][2] += p2 * v4.z; acc[2][3] += p2 * v4.w;
            acc[3][0] += p3 * v4.x; acc[3][1] += p3 * v4.y;
            acc[3][2] += p3 * v4.z; acc[3][3] += p3 * v4.w;
        }
    }

    #pragma unroll
    for (int qi = 0; qi < 4; qi++) {
        const int q = q0 + qi;
        const float inv = 1.0f / sL[q];
        float4 o;
        o.x = acc[qi][0] * inv; o.y = acc[qi][1] * inv;
        o.z = acc[qi][2] * inv; o.w = acc[qi][3] * inv;
        *reinterpret_cast<float4*>(
            &g_att[((size_t)(b * NN + qb + q)) * DM + h * DK + d0]) = o;
    }
}

// ---------------------------------------------------------------------------
extern "C" void kernel_launch(void* const* d_in, const int* in_sizes, int n_in,
                              void* d_out, int out_size)
{
    const float* xq  = (const float*)d_in[0];
    const float* xk  = (const float*)d_in[1];
    const float* xv  = (const float*)d_in[2];
    const float* box = (const float*)d_in[3];
    const int*   msk = (const int*)  d_in[4];
    const float* Wq  = (const float*)d_in[5];
    const float* bq  = (const float*)d_in[6];
    const float* Wk  = (const float*)d_in[7];
    const float* bk  = (const float*)d_in[8];
    const float* Wv  = (const float*)d_in[9];
    const float* bv  = (const float*)d_in[10];
    const float* Wo  = (const float*)d_in[11];
    const float* bo  = (const float*)d_in[12];
    const float* WGw = (const float*)d_in[13];
    const float* WGb = (const float*)d_in[14];

    float* out = (float*)d_out;

    void *pq, *pk, *pv, *pa;
    cudaGetSymbolAddress(&pq, g_q);
    cudaGetSymbolAddress(&pk, g_k);
    cudaGetSymbolAddress(&pv, g_v);
    cudaGetSymbolAddress(&pa, g_att);

    dim3 qkvgrid(GN / 128, GM / 128, 3);    // (4, 32, 3) = 384 blocks

    gemm_qkv<<<qkvgrid, 256>>>(xq, xk, xv, Wq, Wk, Wv, bq, bk, bv,
                               (float*)pq, (float*)pk, (float*)pv);

    geo_bias<<<dim3(NN, BB), 256>>>(box, WGw, WGb);

    attn2<<<dim3(NN / 64, HH, BB), 256>>>(msk);

    gemm_one<<<dim3(GN / 128, GM / 128), 256>>>((const float*)pa, Wo, bo, out);
}